// round 10
// baseline (speedup 1.0000x reference)
#include <cuda_runtime.h>

// FlexQMixer — closed-form reduction.
//
// The reference's attention-mask logic is degenerate: agent_mask and
// entity_mask are all-ones, so `m = attn_mask > 0.5` is all-True, attention
// weights are zeroed by the fully_masked branch, and BOTH post-projection
// `where(agent_mask > 0.5, 0, ·)` guards zero the hypernet outputs entirely.
// Hence hn(i) == 0 for all i, w1 == 1/32, b1 == 0, w_final == 1/32, v == 0,
// and the whole mixer collapses exactly to:
//
//     out[b,t] = elu( (sum_{a=0..7} agent_qs[b,t,a]) / 32 )
//
// R2/R5/R6/R7 evidence: latency/overhead floor (~3% of HBM spec), kernel
// ~4.5 µs under flushed-L2 ncu, total ~6.1-6.5 µs with replay overhead.
// R8 variant: 2 outputs per thread, all 4 LDG.128 FRONT-BATCHED (no
// dependent second round, unlike R2's grid-stride), STG.64, half the CTAs
// (64) -> same chip-wide outstanding loads, less rollout/drain and fewer
// total instructions.

__global__ void __launch_bounds__(256)
flexqmixer_kernel(const float* __restrict__ qs, float* __restrict__ out, int n2) {
    int i = blockIdx.x * blockDim.x + threadIdx.x;  // pair index, 0..16383
    if (i >= n2) return;
    const float4* p = reinterpret_cast<const float4*>(qs) + (size_t)i * 4;
    // Four independent 16B loads, all issued before any use (MLP_p1 = 4).
    float4 a0 = p[0];
    float4 a1 = p[1];
    float4 b0 = p[2];
    float4 b1 = p[3];
    float s0 = ((a0.x + a0.y) + (a0.z + a0.w)) + ((a1.x + a1.y) + (a1.z + a1.w));
    float s1 = ((b0.x + b0.y) + (b0.z + b0.w)) + ((b1.x + b1.y) + (b1.z + b1.w));
    s0 *= 0.03125f;
    s1 *= 0.03125f;
    // elu, alpha=1; branch-free MUFU exp (rel err ~2e-6 << 1e-3 budget).
    float e0 = __expf(s0) - 1.0f;
    float e1 = __expf(s1) - 1.0f;
    float2 r;
    r.x = (s0 > 0.0f) ? s0 : e0;
    r.y = (s1 > 0.0f) ? s1 : e1;
    reinterpret_cast<float2*>(out)[i] = r;  // STG.64
}

extern "C" void kernel_launch(void* const* d_in, const int* in_sizes, int n_in,
                              void* d_out, int out_size) {
    const float* agent_qs = (const float*)d_in[0];  // (128, 256, 8) f32
    float* out = (float*)d_out;                     // (128, 256, 1) f32
    int n2 = out_size / 2;                          // 16384 output pairs
    int threads = 256;
    int blocks = (n2 + threads - 1) / threads;      // 64 blocks
    flexqmixer_kernel<<<blocks, threads>>>(agent_qs, out, n2);
}

// round 13
// speedup vs baseline: 1.4828x; 1.4828x over previous
#include <cuda_runtime.h>

// FlexQMixer — closed-form reduction. FINAL (R5 shape, floor-confirmed).
//
// The reference's attention-mask logic is degenerate: agent_mask and
// entity_mask are all-ones, so `m = attn_mask > 0.5` is all-True, attention
// weights are zeroed by the fully_masked branch, and BOTH post-projection
// `where(agent_mask > 0.5, 0, ·)` guards zero the hypernet outputs entirely.
// Hence hn(i) == 0 for all i, w1 == 1/32, b1 == 0, w_final == 1/32, v == 0,
// and the whole mixer collapses exactly to:
//
//     out[b,t] = elu( (sum_{a=0..7} agent_qs[b,t,a]) / 32 )
//
// Session evidence (R2/R5/R6/R7/R10): every thread-granularity and tail
// variant sits on the same ~4.5 µs ncu plateau at ~3% of HBM spec — the
// binding constraint is CTA rollout + one exposed DRAM latency round +
// graph-replay/launch overhead, none of it kernel-code-addressable at this
// problem size (1.1 MB traffic, 32768 outputs). This is the best-measured
// shape: one output per thread, one memory round (2 front-batched LDG.128),
// single 128x256 wave, no loop.

__global__ void __launch_bounds__(256)
flexqmixer_kernel(const float* __restrict__ qs, float* __restrict__ out, int n) {
    int i = blockIdx.x * blockDim.x + threadIdx.x;
    if (i >= n) return;
    const float4* p = reinterpret_cast<const float4*>(qs) + (size_t)i * 2;
    // Two independent 16B loads, front-batched: one memory round per thread.
    float4 a = p[0];
    float4 b = p[1];
    float s = ((a.x + a.y) + (a.z + a.w)) + ((b.x + b.y) + (b.z + b.w));
    s *= 0.03125f;  // 1/32
    out[i] = (s > 0.0f) ? s : (expf(s) - 1.0f);  // elu, alpha=1
}

extern "C" void kernel_launch(void* const* d_in, const int* in_sizes, int n_in,
                              void* d_out, int out_size) {
    const float* agent_qs = (const float*)d_in[0];  // (128, 256, 8) f32
    float* out = (float*)d_out;                     // (128, 256, 1) f32
    int n = out_size;                               // 32768
    int threads = 256;
    int blocks = (n + threads - 1) / threads;       // 128 blocks, single wave
    flexqmixer_kernel<<<blocks, threads>>>(agent_qs, out, n);
}